// round 1
// baseline (speedup 1.0000x reference)
#include <cuda_runtime.h>
#include <cuda_bf16.h>
#include <math.h>

// Problem constants (QwenGroupedQueryAttention_44100724195922)
#define BB   2
#define TT   2048
#define EE   2048
#define HH   16
#define DD   128
#define GG   4
#define NKVH 4
#define KVD  512
#define N1   3072          // E + 2*KV_DIM
#define MM   4096          // B*T

// Scratch (static __device__ — no allocation allowed)
__device__ float g_qkv[(size_t)MM * N1];            // 50.3 MB
__device__ float g_k[(size_t)BB * NKVH * TT * DD];  // 8 MB (rope'd, expanded-by-index)
__device__ float g_v[(size_t)BB * NKVH * TT * DD];  // 8 MB
__device__ float g_y[(size_t)MM * EE];              // 33.6 MB

// ---------------------------------------------------------------------------
// SGEMM: C[M,N] = A[M,K] @ B[K,N] (+bias). 128x128 tile, BK=16, 8x8 micro.
// All dims divisible by tile sizes for this problem — no bounds checks.
// ---------------------------------------------------------------------------
__global__ __launch_bounds__(256)
void sgemm128(const float* __restrict__ A, const float* __restrict__ Bm,
              const float* __restrict__ bias, float* __restrict__ C,
              int M, int N, int K) {
    __shared__ __align__(16) float As[16][132];  // [k][m], padded
    __shared__ __align__(16) float Bs[16][128];  // [k][n]

    int tid = threadIdx.x;
    int tx = tid & 15, ty = tid >> 4;
    int bm = blockIdx.y * 128, bn = blockIdx.x * 128;

    float acc[8][8];
#pragma unroll
    for (int i = 0; i < 8; i++)
#pragma unroll
        for (int j = 0; j < 8; j++) acc[i][j] = 0.f;

    int aRow0 = tid >> 2;            // 0..63 (and +64)
    int aCol0 = (tid & 3) * 4;       // 0,4,8,12
    int bRow0 = tid >> 5;            // 0..7 (and +8)
    int bCol0 = (tid & 31) * 4;      // 0..124

    for (int k0 = 0; k0 < K; k0 += 16) {
#pragma unroll
        for (int i = 0; i < 2; i++) {
            int r = aRow0 + i * 64;
            float4 a = *(const float4*)(A + (size_t)(bm + r) * K + k0 + aCol0);
            As[aCol0 + 0][r] = a.x;
            As[aCol0 + 1][r] = a.y;
            As[aCol0 + 2][r] = a.z;
            As[aCol0 + 3][r] = a.w;
        }
#pragma unroll
        for (int i = 0; i < 2; i++) {
            int r = bRow0 + i * 8;
            *(float4*)(&Bs[r][bCol0]) =
                *(const float4*)(Bm + (size_t)(k0 + r) * N + bn + bCol0);
        }
        __syncthreads();

#pragma unroll
        for (int kk = 0; kk < 16; kk++) {
            float a[8], b[8];
            *(float4*)(a)     = *(const float4*)(&As[kk][ty * 8]);
            *(float4*)(a + 4) = *(const float4*)(&As[kk][ty * 8 + 4]);
            *(float4*)(b)     = *(const float4*)(&Bs[kk][tx * 8]);
            *(float4*)(b + 4) = *(const float4*)(&Bs[kk][tx * 8 + 4]);
#pragma unroll
            for (int i = 0; i < 8; i++)
#pragma unroll
                for (int j = 0; j < 8; j++) acc[i][j] += a[i] * b[j];
        }
        __syncthreads();
    }

#pragma unroll
    for (int i = 0; i < 8; i++) {
        int row = bm + ty * 8 + i;
#pragma unroll
        for (int j = 0; j < 8; j += 4) {
            int col = bn + tx * 8 + j;
            float4 o = make_float4(acc[i][j], acc[i][j + 1], acc[i][j + 2], acc[i][j + 3]);
            if (bias) {
                o.x += bias[col];     o.y += bias[col + 1];
                o.z += bias[col + 2]; o.w += bias[col + 3];
            }
            *(float4*)(C + (size_t)row * N + col) = o;
        }
    }
}

// ---------------------------------------------------------------------------
// RoPE + split: K and V both get RoPE (per reference); Q does NOT.
// Writes K,V as [B, NKV, T, D].
// grid: (T, B*NKV), block 64 (one thread per rotation pair)
// ---------------------------------------------------------------------------
__global__ __launch_bounds__(64)
void rope_split_kernel(const float* __restrict__ qkv,
                       const float* __restrict__ fc,
                       const float* __restrict__ fs,
                       float* __restrict__ Kg, float* __restrict__ Vg) {
    int t = blockIdx.x;
    int bk = blockIdx.y;
    int b = bk / NKVH, kv = bk % NKVH;
    int i = threadIdx.x;  // 0..63

    float c = fc[t * 64 + i];
    float s = fs[t * 64 + i];
    const float* row = qkv + ((size_t)(b * TT + t)) * N1;

    float k0 = row[EE + kv * DD + 2 * i];
    float k1 = row[EE + kv * DD + 2 * i + 1];
    float v0 = row[EE + KVD + kv * DD + 2 * i];
    float v1 = row[EE + KVD + kv * DD + 2 * i + 1];

    size_t o = ((size_t)(b * NKVH + kv) * TT + t) * DD + 2 * i;
    Kg[o]     = k0 * c - k1 * s;
    Kg[o + 1] = k0 * s + k1 * c;
    Vg[o]     = v0 * c - v1 * s;
    Vg[o + 1] = v0 * s + v1 * c;
}

// ---------------------------------------------------------------------------
// Flash attention (fp32, causal, GQA). 64-query tile per block, 256 threads.
// Q read directly from qkv (no rope on Q). Smem layouts transposed so the
// inner loops are float4 LDS + FFMA.
// grid: (T/64, B*H)
// ---------------------------------------------------------------------------
#define QT_S 68    // padded stride for [d][t] tiles
#define VS_S 132   // padded stride for [t][d] tile
#define SMEM_FLOATS (128 * QT_S + 128 * QT_S + 64 * VS_S + 64 * QT_S)

__global__ __launch_bounds__(256, 1)
void attn_kernel(const float* __restrict__ qkv,
                 const float* __restrict__ Kg,
                 const float* __restrict__ Vg,
                 float* __restrict__ Y) {
    extern __shared__ __align__(16) float sm[];
    float* Qt = sm;                       // [128][68]  (d-major)
    float* Kt = Qt + 128 * QT_S;          // [128][68]  (d-major)
    float* Vs = Kt + 128 * QT_S;          // [64][132]  (t-major)
    float* Pt = Vs + 64 * VS_S;           // [64][68]   (k-major)

    int tid = threadIdx.x;
    int tx = tid & 15, ty = tid >> 4;
    int qtile = blockIdx.x;
    int bh = blockIdx.y;
    int b = bh / HH, h = bh % HH;
    int kv = h / GG;

    const float* qbase = qkv + ((size_t)(b * TT + qtile * 64)) * N1 + h * DD;
    {
        int d = (tid & 31) * 4;
        int rr0 = tid >> 5;
#pragma unroll
        for (int rr = 0; rr < 64; rr += 8) {
            int r = rr0 + rr;
            float4 q = *(const float4*)(qbase + (size_t)r * N1 + d);
            Qt[(d + 0) * QT_S + r] = q.x;
            Qt[(d + 1) * QT_S + r] = q.y;
            Qt[(d + 2) * QT_S + r] = q.z;
            Qt[(d + 3) * QT_S + r] = q.w;
        }
    }

    const float scale = 0.08838834764831845f;  // 1/sqrt(128)
    float m[4], l[4], acc[4][8];
#pragma unroll
    for (int i = 0; i < 4; i++) {
        m[i] = -1e30f; l[i] = 0.f;
#pragma unroll
        for (int j = 0; j < 8; j++) acc[i][j] = 0.f;
    }

    int r0 = ty * 4;
    int c0 = tx * 4;
    int co = tx * 8;
    const float* kbase = Kg + ((size_t)(b * NKVH + kv) * TT) * DD;
    const float* vbase = Vg + ((size_t)(b * NKVH + kv) * TT) * DD;

    for (int jt = 0; jt <= qtile; jt++) {
        __syncthreads();  // previous PV done before overwriting Kt/Vs/Pt
        {
            int d = (tid & 31) * 4;
            int rr0 = tid >> 5;
#pragma unroll
            for (int rr = 0; rr < 64; rr += 8) {
                int c = rr0 + rr;
                const float* krow = kbase + (size_t)(jt * 64 + c) * DD + d;
                float4 k4 = *(const float4*)krow;
                Kt[(d + 0) * QT_S + c] = k4.x;
                Kt[(d + 1) * QT_S + c] = k4.y;
                Kt[(d + 2) * QT_S + c] = k4.z;
                Kt[(d + 3) * QT_S + c] = k4.w;
                const float* vrow = vbase + (size_t)(jt * 64 + c) * DD + d;
                *(float4*)(Vs + c * VS_S + d) = *(const float4*)vrow;
            }
        }
        __syncthreads();

        // S = Q @ K^T (64x64), each thread 4x4
        float s[4][4];
#pragma unroll
        for (int i = 0; i < 4; i++)
#pragma unroll
            for (int j = 0; j < 4; j++) s[i][j] = 0.f;

#pragma unroll 4
        for (int kk = 0; kk < 128; kk++) {
            float4 q4 = *(const float4*)(Qt + kk * QT_S + r0);
            float4 k4 = *(const float4*)(Kt + kk * QT_S + c0);
            float qa[4] = {q4.x, q4.y, q4.z, q4.w};
            float ka[4] = {k4.x, k4.y, k4.z, k4.w};
#pragma unroll
            for (int i = 0; i < 4; i++)
#pragma unroll
                for (int j = 0; j < 4; j++) s[i][j] += qa[i] * ka[j];
        }

        int qg0 = qtile * 64 + r0;
        int kg0 = jt * 64 + c0;
#pragma unroll
        for (int i = 0; i < 4; i++)
#pragma unroll
            for (int j = 0; j < 4; j++) {
                s[i][j] *= scale;
                if (kg0 + j > qg0 + i) s[i][j] = -1e30f;
            }

        // online softmax per row (row spread over 16 tx lanes)
#pragma unroll
        for (int i = 0; i < 4; i++) {
            float rm = fmaxf(fmaxf(s[i][0], s[i][1]), fmaxf(s[i][2], s[i][3]));
#pragma unroll
            for (int off = 1; off < 16; off <<= 1)
                rm = fmaxf(rm, __shfl_xor_sync(0xffffffffu, rm, off));
            float mn = fmaxf(m[i], rm);
            float corr = __expf(m[i] - mn);
            m[i] = mn;
            l[i] *= corr;
#pragma unroll
            for (int j = 0; j < 8; j++) acc[i][j] *= corr;
            float p[4], rs = 0.f;
#pragma unroll
            for (int j = 0; j < 4; j++) {
                p[j] = __expf(s[i][j] - mn);
                rs += p[j];
            }
#pragma unroll
            for (int off = 1; off < 16; off <<= 1)
                rs += __shfl_xor_sync(0xffffffffu, rs, off);
            l[i] += rs;
#pragma unroll
            for (int j = 0; j < 4; j++) Pt[(c0 + j) * QT_S + (r0 + i)] = p[j];
        }
        __syncthreads();

        // O += P @ V  (64x64 @ 64x128), each thread 4x8
#pragma unroll 2
        for (int kk = 0; kk < 64; kk++) {
            float4 p4 = *(const float4*)(Pt + kk * QT_S + r0);
            float4 va = *(const float4*)(Vs + kk * VS_S + co);
            float4 vb = *(const float4*)(Vs + kk * VS_S + co + 4);
            float pa[4] = {p4.x, p4.y, p4.z, p4.w};
            float v8[8] = {va.x, va.y, va.z, va.w, vb.x, vb.y, vb.z, vb.w};
#pragma unroll
            for (int i = 0; i < 4; i++)
#pragma unroll
                for (int j = 0; j < 8; j++) acc[i][j] += pa[i] * v8[j];
        }
    }

    // finalize: divide by l, write Y[b][t][h*D + d]
#pragma unroll
    for (int i = 0; i < 4; i++) {
        float inv = 1.f / l[i];
        int t = qtile * 64 + r0 + i;
        float* yrow = Y + ((size_t)(b * TT + t)) * EE + h * DD + co;
        float4 o1 = make_float4(acc[i][0] * inv, acc[i][1] * inv,
                                acc[i][2] * inv, acc[i][3] * inv);
        float4 o2 = make_float4(acc[i][4] * inv, acc[i][5] * inv,
                                acc[i][6] * inv, acc[i][7] * inv);
        *(float4*)(yrow) = o1;
        *(float4*)(yrow + 4) = o2;
    }
}

// ---------------------------------------------------------------------------
extern "C" void kernel_launch(void* const* d_in, const int* in_sizes, int n_in,
                              void* d_out, int out_size) {
    const float* x  = (const float*)d_in[0];
    const float* Wa = (const float*)d_in[1];
    const float* ba = (const float*)d_in[2];
    const float* Wp = (const float*)d_in[3];
    const float* fc = (const float*)d_in[4];
    const float* fs = (const float*)d_in[5];
    float* out = (float*)d_out;

    float *qkv, *kg, *vg, *yb;
    cudaGetSymbolAddress((void**)&qkv, g_qkv);
    cudaGetSymbolAddress((void**)&kg, g_k);
    cudaGetSymbolAddress((void**)&vg, g_v);
    cudaGetSymbolAddress((void**)&yb, g_y);

    // 1) QKV GEMM (+bias)
    sgemm128<<<dim3(N1 / 128, MM / 128), 256>>>(x, Wa, ba, qkv, MM, N1, EE);

    // 2) RoPE on K and V, split into [B,NKV,T,D]
    rope_split_kernel<<<dim3(TT, BB * NKVH), 64>>>(qkv, fc, fs, kg, vg);

    // 3) causal GQA flash attention
    int smem_bytes = SMEM_FLOATS * (int)sizeof(float);
    cudaFuncSetAttribute(attn_kernel, cudaFuncAttributeMaxDynamicSharedMemorySize,
                         smem_bytes);
    attn_kernel<<<dim3(TT / 64, BB * HH), 256, smem_bytes>>>(qkv, kg, vg, yb);

    // 4) output projection
    sgemm128<<<dim3(EE / 128, MM / 128), 256>>>(yb, Wp, nullptr, out, MM, EE, EE);
}

// round 2
// speedup vs baseline: 1.4793x; 1.4793x over previous
#include <cuda_runtime.h>
#include <cuda_bf16.h>
#include <math.h>
#include <stdint.h>

// Problem constants (QwenGroupedQueryAttention_44100724195922)
#define BB   2
#define TT   2048
#define EE   2048
#define HH   16
#define DD   128
#define GG   4
#define NKVH 4
#define KVD  512
#define N1   3072          // E + 2*KV_DIM
#define MM   4096          // B*T

// Scratch (static __device__ — no allocation allowed)
__device__ float g_qkv[(size_t)MM * N1];            // 50.3 MB
__device__ float g_k[(size_t)BB * NKVH * TT * DD];  // 8 MB
__device__ float g_v[(size_t)BB * NKVH * TT * DD];  // 8 MB
__device__ float g_y[(size_t)MM * EE];              // 33.6 MB

// ---------------------------------------------------------------------------
// TF32 tensor-core GEMM: C[M,N] = A[M,K] @ B[K,N] (+bias)
// 128x128 block tile, BK=16, double-buffered smem, mma.sync.m16n8k8.tf32.
// Inputs converted fp32->tf32 (round-to-nearest) at the staging step.
// Requires M%128==0, N%128==0, K%16==0 (true for all calls here).
// ---------------------------------------------------------------------------
#define GS 136  // smem row stride (8 mod 32 -> conflict-free fragment loads)

__device__ __forceinline__ uint32_t f2tf32(float x) {
    uint32_t r;
    asm("cvt.rna.tf32.f32 %0, %1;" : "=r"(r) : "f"(x));
    return r;
}

__device__ __forceinline__ void mma_tf32(float c[4], const uint32_t a[4],
                                         const uint32_t b[2]) {
    asm volatile(
        "mma.sync.aligned.m16n8k8.row.col.f32.tf32.tf32.f32 "
        "{%0,%1,%2,%3}, {%4,%5,%6,%7}, {%8,%9}, {%0,%1,%2,%3};"
        : "+f"(c[0]), "+f"(c[1]), "+f"(c[2]), "+f"(c[3])
        : "r"(a[0]), "r"(a[1]), "r"(a[2]), "r"(a[3]), "r"(b[0]), "r"(b[1]));
}

__global__ __launch_bounds__(256)
void gemm_tf32(const float* __restrict__ A, const float* __restrict__ Bm,
               const float* __restrict__ bias, float* __restrict__ C,
               int M, int N, int K) {
    __shared__ uint32_t As[2][16][GS];  // [k][m]
    __shared__ uint32_t Bs[2][16][GS];  // [k][n]

    const int tid = threadIdx.x;
    const int lane = tid & 31;
    const int wid = tid >> 5;
    const int wm = wid >> 2;         // 0..1 -> m offset 64*wm
    const int wn = wid & 3;          // 0..3 -> n offset 32*wn
    const int bm = blockIdx.y * 128, bn = blockIdx.x * 128;

    float acc[4][4][4];
#pragma unroll
    for (int mi = 0; mi < 4; mi++)
#pragma unroll
        for (int ni = 0; ni < 4; ni++)
#pragma unroll
            for (int r = 0; r < 4; r++) acc[mi][ni][r] = 0.f;

    // staging index precompute
    const int aRow = tid >> 2;            // 0..63 (+64)
    const int aCol = (tid & 3) * 4;       // 0,4,8,12
    const int bRow = tid >> 5;            // 0..7 (+8)
    const int bCol = (tid & 31) * 4;      // 0..124

    auto stage = [&](int kt, int buf) {
#pragma unroll
        for (int i = 0; i < 2; i++) {
            int r = aRow + i * 64;
            float4 a = *(const float4*)(A + (size_t)(bm + r) * K + kt + aCol);
            As[buf][aCol + 0][r] = f2tf32(a.x);
            As[buf][aCol + 1][r] = f2tf32(a.y);
            As[buf][aCol + 2][r] = f2tf32(a.z);
            As[buf][aCol + 3][r] = f2tf32(a.w);
        }
#pragma unroll
        for (int i = 0; i < 2; i++) {
            int r = bRow + i * 8;
            float4 b = *(const float4*)(Bm + (size_t)(kt + r) * N + bn + bCol);
            uint4 t;
            t.x = f2tf32(b.x); t.y = f2tf32(b.y);
            t.z = f2tf32(b.z); t.w = f2tf32(b.w);
            *(uint4*)(&Bs[buf][r][bCol]) = t;
        }
    };

    stage(0, 0);
    __syncthreads();

    const int nkt = K / 16;
    for (int kt = 0; kt < nkt; kt++) {
        int cur = kt & 1;
        if (kt + 1 < nkt) stage((kt + 1) * 16, cur ^ 1);

#pragma unroll
        for (int s = 0; s < 2; s++) {
            int kb = s * 8 + (lane & 3);
            uint32_t af[4][4];
#pragma unroll
            for (int mi = 0; mi < 4; mi++) {
                int r = wm * 64 + mi * 16 + (lane >> 2);
                af[mi][0] = As[cur][kb][r];
                af[mi][1] = As[cur][kb][r + 8];
                af[mi][2] = As[cur][kb + 4][r];
                af[mi][3] = As[cur][kb + 4][r + 8];
            }
            uint32_t bf[4][2];
#pragma unroll
            for (int ni = 0; ni < 4; ni++) {
                int c = wn * 32 + ni * 8 + (lane >> 2);
                bf[ni][0] = Bs[cur][kb][c];
                bf[ni][1] = Bs[cur][kb + 4][c];
            }
#pragma unroll
            for (int mi = 0; mi < 4; mi++)
#pragma unroll
                for (int ni = 0; ni < 4; ni++)
                    mma_tf32(acc[mi][ni], af[mi], bf[ni]);
        }
        __syncthreads();
    }

    // epilogue: acc layout rows lane/4 (+8), cols 2*(lane%4) (+1)
#pragma unroll
    for (int mi = 0; mi < 4; mi++) {
        int row = bm + wm * 64 + mi * 16 + (lane >> 2);
#pragma unroll
        for (int ni = 0; ni < 4; ni++) {
            int col = bn + wn * 32 + ni * 8 + 2 * (lane & 3);
            float bx = 0.f, by = 0.f;
            if (bias) { bx = bias[col]; by = bias[col + 1]; }
            float2 o0 = make_float2(acc[mi][ni][0] + bx, acc[mi][ni][1] + by);
            float2 o1 = make_float2(acc[mi][ni][2] + bx, acc[mi][ni][3] + by);
            *(float2*)(C + (size_t)row * N + col) = o0;
            *(float2*)(C + (size_t)(row + 8) * N + col) = o1;
        }
    }
}

// ---------------------------------------------------------------------------
// RoPE + split: K and V both get RoPE (per reference); Q does NOT.
// Writes K,V as [B, NKV, T, D].  grid: (T, B*NKV), block 64.
// ---------------------------------------------------------------------------
__global__ __launch_bounds__(64)
void rope_split_kernel(const float* __restrict__ qkv,
                       const float* __restrict__ fc,
                       const float* __restrict__ fs,
                       float* __restrict__ Kg, float* __restrict__ Vg) {
    int t = blockIdx.x;
    int bk = blockIdx.y;
    int b = bk / NKVH, kv = bk % NKVH;
    int i = threadIdx.x;  // 0..63

    float c = fc[t * 64 + i];
    float s = fs[t * 64 + i];
    const float* row = qkv + ((size_t)(b * TT + t)) * N1;

    float k0 = row[EE + kv * DD + 2 * i];
    float k1 = row[EE + kv * DD + 2 * i + 1];
    float v0 = row[EE + KVD + kv * DD + 2 * i];
    float v1 = row[EE + KVD + kv * DD + 2 * i + 1];

    size_t o = ((size_t)(b * NKVH + kv) * TT + t) * DD + 2 * i;
    Kg[o]     = k0 * c - k1 * s;
    Kg[o + 1] = k0 * s + k1 * c;
    Vg[o]     = v0 * c - v1 * s;
    Vg[o + 1] = v0 * s + v1 * c;
}

// ---------------------------------------------------------------------------
// Flash attention (fp32, causal, GQA). 64-query tile per block, 256 threads.
// ---------------------------------------------------------------------------
#define QT_S 68
#define VS_S 132
#define SMEM_FLOATS (128 * QT_S + 128 * QT_S + 64 * VS_S + 64 * QT_S)

__global__ __launch_bounds__(256, 1)
void attn_kernel(const float* __restrict__ qkv,
                 const float* __restrict__ Kg,
                 const float* __restrict__ Vg,
                 float* __restrict__ Y) {
    extern __shared__ __align__(16) float sm[];
    float* Qt = sm;                       // [128][68]  (d-major)
    float* Kt = Qt + 128 * QT_S;          // [128][68]  (d-major)
    float* Vs = Kt + 128 * QT_S;          // [64][132]  (t-major)
    float* Pt = Vs + 64 * VS_S;           // [64][68]   (k-major)

    int tid = threadIdx.x;
    int tx = tid & 15, ty = tid >> 4;
    int qtile = blockIdx.x;
    int bh = blockIdx.y;
    int b = bh / HH, h = bh % HH;
    int kv = h / GG;

    const float* qbase = qkv + ((size_t)(b * TT + qtile * 64)) * N1 + h * DD;
    {
        int d = (tid & 31) * 4;
        int rr0 = tid >> 5;
#pragma unroll
        for (int rr = 0; rr < 64; rr += 8) {
            int r = rr0 + rr;
            float4 q = *(const float4*)(qbase + (size_t)r * N1 + d);
            Qt[(d + 0) * QT_S + r] = q.x;
            Qt[(d + 1) * QT_S + r] = q.y;
            Qt[(d + 2) * QT_S + r] = q.z;
            Qt[(d + 3) * QT_S + r] = q.w;
        }
    }

    const float scale = 0.08838834764831845f;  // 1/sqrt(128)
    float m[4], l[4], acc[4][8];
#pragma unroll
    for (int i = 0; i < 4; i++) {
        m[i] = -1e30f; l[i] = 0.f;
#pragma unroll
        for (int j = 0; j < 8; j++) acc[i][j] = 0.f;
    }

    int r0 = ty * 4;
    int c0 = tx * 4;
    int co = tx * 8;
    const float* kbase = Kg + ((size_t)(b * NKVH + kv) * TT) * DD;
    const float* vbase = Vg + ((size_t)(b * NKVH + kv) * TT) * DD;

    for (int jt = 0; jt <= qtile; jt++) {
        __syncthreads();
        {
            int d = (tid & 31) * 4;
            int rr0 = tid >> 5;
#pragma unroll
            for (int rr = 0; rr < 64; rr += 8) {
                int c = rr0 + rr;
                const float* krow = kbase + (size_t)(jt * 64 + c) * DD + d;
                float4 k4 = *(const float4*)krow;
                Kt[(d + 0) * QT_S + c] = k4.x;
                Kt[(d + 1) * QT_S + c] = k4.y;
                Kt[(d + 2) * QT_S + c] = k4.z;
                Kt[(d + 3) * QT_S + c] = k4.w;
                const float* vrow = vbase + (size_t)(jt * 64 + c) * DD + d;
                *(float4*)(Vs + c * VS_S + d) = *(const float4*)vrow;
            }
        }
        __syncthreads();

        float s[4][4];
#pragma unroll
        for (int i = 0; i < 4; i++)
#pragma unroll
            for (int j = 0; j < 4; j++) s[i][j] = 0.f;

#pragma unroll 4
        for (int kk = 0; kk < 128; kk++) {
            float4 q4 = *(const float4*)(Qt + kk * QT_S + r0);
            float4 k4 = *(const float4*)(Kt + kk * QT_S + c0);
            float qa[4] = {q4.x, q4.y, q4.z, q4.w};
            float ka[4] = {k4.x, k4.y, k4.z, k4.w};
#pragma unroll
            for (int i = 0; i < 4; i++)
#pragma unroll
                for (int j = 0; j < 4; j++) s[i][j] += qa[i] * ka[j];
        }

        int qg0 = qtile * 64 + r0;
        int kg0 = jt * 64 + c0;
#pragma unroll
        for (int i = 0; i < 4; i++)
#pragma unroll
            for (int j = 0; j < 4; j++) {
                s[i][j] *= scale;
                if (kg0 + j > qg0 + i) s[i][j] = -1e30f;
            }

#pragma unroll
        for (int i = 0; i < 4; i++) {
            float rm = fmaxf(fmaxf(s[i][0], s[i][1]), fmaxf(s[i][2], s[i][3]));
#pragma unroll
            for (int off = 1; off < 16; off <<= 1)
                rm = fmaxf(rm, __shfl_xor_sync(0xffffffffu, rm, off));
            float mn = fmaxf(m[i], rm);
            float corr = __expf(m[i] - mn);
            m[i] = mn;
            l[i] *= corr;
#pragma unroll
            for (int j = 0; j < 8; j++) acc[i][j] *= corr;
            float p[4], rs = 0.f;
#pragma unroll
            for (int j = 0; j < 4; j++) {
                p[j] = __expf(s[i][j] - mn);
                rs += p[j];
            }
#pragma unroll
            for (int off = 1; off < 16; off <<= 1)
                rs += __shfl_xor_sync(0xffffffffu, rs, off);
            l[i] += rs;
#pragma unroll
            for (int j = 0; j < 4; j++) Pt[(c0 + j) * QT_S + (r0 + i)] = p[j];
        }
        __syncthreads();

#pragma unroll 2
        for (int kk = 0; kk < 64; kk++) {
            float4 p4 = *(const float4*)(Pt + kk * QT_S + r0);
            float4 va = *(const float4*)(Vs + kk * VS_S + co);
            float4 vb = *(const float4*)(Vs + kk * VS_S + co + 4);
            float pa[4] = {p4.x, p4.y, p4.z, p4.w};
            float v8[8] = {va.x, va.y, va.z, va.w, vb.x, vb.y, vb.z, vb.w};
#pragma unroll
            for (int i = 0; i < 4; i++)
#pragma unroll
                for (int j = 0; j < 8; j++) acc[i][j] += pa[i] * v8[j];
        }
    }

#pragma unroll
    for (int i = 0; i < 4; i++) {
        float inv = 1.f / l[i];
        int t = qtile * 64 + r0 + i;
        float* yrow = Y + ((size_t)(b * TT + t)) * EE + h * DD + co;
        float4 o1 = make_float4(acc[i][0] * inv, acc[i][1] * inv,
                                acc[i][2] * inv, acc[i][3] * inv);
        float4 o2 = make_float4(acc[i][4] * inv, acc[i][5] * inv,
                                acc[i][6] * inv, acc[i][7] * inv);
        *(float4*)(yrow) = o1;
        *(float4*)(yrow + 4) = o2;
    }
}

// ---------------------------------------------------------------------------
extern "C" void kernel_launch(void* const* d_in, const int* in_sizes, int n_in,
                              void* d_out, int out_size) {
    const float* x  = (const float*)d_in[0];
    const float* Wa = (const float*)d_in[1];
    const float* ba = (const float*)d_in[2];
    const float* Wp = (const float*)d_in[3];
    const float* fc = (const float*)d_in[4];
    const float* fs = (const float*)d_in[5];
    float* out = (float*)d_out;

    float *qkv, *kg, *vg, *yb;
    cudaGetSymbolAddress((void**)&qkv, g_qkv);
    cudaGetSymbolAddress((void**)&kg, g_k);
    cudaGetSymbolAddress((void**)&vg, g_v);
    cudaGetSymbolAddress((void**)&yb, g_y);

    // 1) QKV GEMM (+bias) — tf32 tensor cores
    gemm_tf32<<<dim3(N1 / 128, MM / 128), 256>>>(x, Wa, ba, qkv, MM, N1, EE);

    // 2) RoPE on K and V, split into [B,NKV,T,D]
    rope_split_kernel<<<dim3(TT, BB * NKVH), 64>>>(qkv, fc, fs, kg, vg);

    // 3) causal GQA flash attention (fp32 — tensor-core conversion next)
    int smem_bytes = SMEM_FLOATS * (int)sizeof(float);
    cudaFuncSetAttribute(attn_kernel, cudaFuncAttributeMaxDynamicSharedMemorySize,
                         smem_bytes);
    attn_kernel<<<dim3(TT / 64, BB * HH), 256, smem_bytes>>>(qkv, kg, vg, yb);

    // 4) output projection — tf32 tensor cores
    gemm_tf32<<<dim3(EE / 128, MM / 128), 256>>>(yb, Wp, nullptr, out, MM, EE, EE);
}

// round 3
// speedup vs baseline: 3.0624x; 2.0701x over previous
#include <cuda_runtime.h>
#include <cuda_bf16.h>
#include <math.h>
#include <stdint.h>

// Problem constants (QwenGroupedQueryAttention_44100724195922)
#define BB   2
#define TT   2048
#define EE   2048
#define HH   16
#define DD   128
#define GG   4
#define NKVH 4
#define KVD  512
#define N1   3072
#define MM   4096

__device__ float g_qkv[(size_t)MM * N1];
__device__ float g_k[(size_t)BB * NKVH * TT * DD];   // tf32 bits
__device__ float g_v[(size_t)BB * NKVH * TT * DD];   // tf32 bits
__device__ float g_y[(size_t)MM * EE];

__device__ __forceinline__ uint32_t f2tf32(float x) {
    uint32_t r;
    asm("cvt.rna.tf32.f32 %0, %1;" : "=r"(r) : "f"(x));
    return r;
}

__device__ __forceinline__ void mma_tf32(float c[4], const uint32_t a[4],
                                         const uint32_t b[2]) {
    asm volatile(
        "mma.sync.aligned.m16n8k8.row.col.f32.tf32.tf32.f32 "
        "{%0,%1,%2,%3}, {%4,%5,%6,%7}, {%8,%9}, {%0,%1,%2,%3};"
        : "+f"(c[0]), "+f"(c[1]), "+f"(c[2]), "+f"(c[3])
        : "r"(a[0]), "r"(a[1]), "r"(a[2]), "r"(a[3]), "r"(b[0]), "r"(b[1]));
}

// ---------------------------------------------------------------------------
// TF32 GEMM: C[M,N] = A[M,K] @ B[K,N] (+bias). 128x128, BK=16, double-buffered.
// ---------------------------------------------------------------------------
#define GS 136

__global__ __launch_bounds__(256)
void gemm_tf32(const float* __restrict__ A, const float* __restrict__ Bm,
               const float* __restrict__ bias, float* __restrict__ C,
               int M, int N, int K) {
    __shared__ uint32_t As[2][16][GS];
    __shared__ uint32_t Bs[2][16][GS];

    const int tid = threadIdx.x;
    const int lane = tid & 31;
    const int wid = tid >> 5;
    const int wm = wid >> 2;
    const int wn = wid & 3;
    const int bm = blockIdx.y * 128, bn = blockIdx.x * 128;

    float acc[4][4][4];
#pragma unroll
    for (int mi = 0; mi < 4; mi++)
#pragma unroll
        for (int ni = 0; ni < 4; ni++)
#pragma unroll
            for (int r = 0; r < 4; r++) acc[mi][ni][r] = 0.f;

    const int aRow = tid >> 2;
    const int aCol = (tid & 3) * 4;
    const int bRow = tid >> 5;
    const int bCol = (tid & 31) * 4;

    auto stage = [&](int kt, int buf) {
#pragma unroll
        for (int i = 0; i < 2; i++) {
            int r = aRow + i * 64;
            float4 a = *(const float4*)(A + (size_t)(bm + r) * K + kt + aCol);
            As[buf][aCol + 0][r] = f2tf32(a.x);
            As[buf][aCol + 1][r] = f2tf32(a.y);
            As[buf][aCol + 2][r] = f2tf32(a.z);
            As[buf][aCol + 3][r] = f2tf32(a.w);
        }
#pragma unroll
        for (int i = 0; i < 2; i++) {
            int r = bRow + i * 8;
            float4 b = *(const float4*)(Bm + (size_t)(kt + r) * N + bn + bCol);
            uint4 t;
            t.x = f2tf32(b.x); t.y = f2tf32(b.y);
            t.z = f2tf32(b.z); t.w = f2tf32(b.w);
            *(uint4*)(&Bs[buf][r][bCol]) = t;
        }
    };

    stage(0, 0);
    __syncthreads();

    const int nkt = K / 16;
    for (int kt = 0; kt < nkt; kt++) {
        int cur = kt & 1;
        if (kt + 1 < nkt) stage((kt + 1) * 16, cur ^ 1);

#pragma unroll
        for (int s = 0; s < 2; s++) {
            int kb = s * 8 + (lane & 3);
            uint32_t af[4][4];
#pragma unroll
            for (int mi = 0; mi < 4; mi++) {
                int r = wm * 64 + mi * 16 + (lane >> 2);
                af[mi][0] = As[cur][kb][r];
                af[mi][1] = As[cur][kb][r + 8];
                af[mi][2] = As[cur][kb + 4][r];
                af[mi][3] = As[cur][kb + 4][r + 8];
            }
            uint32_t bf[4][2];
#pragma unroll
            for (int ni = 0; ni < 4; ni++) {
                int c = wn * 32 + ni * 8 + (lane >> 2);
                bf[ni][0] = Bs[cur][kb][c];
                bf[ni][1] = Bs[cur][kb + 4][c];
            }
#pragma unroll
            for (int mi = 0; mi < 4; mi++)
#pragma unroll
                for (int ni = 0; ni < 4; ni++)
                    mma_tf32(acc[mi][ni], af[mi], bf[ni]);
        }
        __syncthreads();
    }

#pragma unroll
    for (int mi = 0; mi < 4; mi++) {
        int row = bm + wm * 64 + mi * 16 + (lane >> 2);
#pragma unroll
        for (int ni = 0; ni < 4; ni++) {
            int col = bn + wn * 32 + ni * 8 + 2 * (lane & 3);
            float bx = 0.f, by = 0.f;
            if (bias) { bx = bias[col]; by = bias[col + 1]; }
            float2 o0 = make_float2(acc[mi][ni][0] + bx, acc[mi][ni][1] + by);
            float2 o1 = make_float2(acc[mi][ni][2] + bx, acc[mi][ni][3] + by);
            *(float2*)(C + (size_t)row * N + col) = o0;
            *(float2*)(C + (size_t)(row + 8) * N + col) = o1;
        }
    }
}

// ---------------------------------------------------------------------------
// RoPE on K and V (per reference), split into [B,NKV,T,D], stored as TF32 bits.
// ---------------------------------------------------------------------------
__global__ __launch_bounds__(64)
void rope_split_kernel(const float* __restrict__ qkv,
                       const float* __restrict__ fc,
                       const float* __restrict__ fs,
                       float* __restrict__ Kg, float* __restrict__ Vg) {
    int t = blockIdx.x;
    int bk = blockIdx.y;
    int b = bk / NKVH, kv = bk % NKVH;
    int i = threadIdx.x;

    float c = fc[t * 64 + i];
    float s = fs[t * 64 + i];
    const float* row = qkv + ((size_t)(b * TT + t)) * N1;

    float k0 = row[EE + kv * DD + 2 * i];
    float k1 = row[EE + kv * DD + 2 * i + 1];
    float v0 = row[EE + KVD + kv * DD + 2 * i];
    float v1 = row[EE + KVD + kv * DD + 2 * i + 1];

    size_t o = ((size_t)(b * NKVH + kv) * TT + t) * DD + 2 * i;
    Kg[o]     = __uint_as_float(f2tf32(k0 * c - k1 * s));
    Kg[o + 1] = __uint_as_float(f2tf32(k0 * s + k1 * c));
    Vg[o]     = __uint_as_float(f2tf32(v0 * c - v1 * s));
    Vg[o + 1] = __uint_as_float(f2tf32(v0 * s + v1 * c));
}

// ---------------------------------------------------------------------------
// TF32 tensor-core flash attention. 256 thr / 8 warps, Q tile 128, KV tile 64.
// Warp w owns rows [w*16, w*16+16). S and PV on mma.m16n8k8.tf32.
// ---------------------------------------------------------------------------
#define QS_S 132
#define KS_S 132
#define VS_S2 136
#define PS_S 68
#define SM_Q  0
#define SM_K  (128 * QS_S)
#define SM_V  (SM_K + 64 * KS_S)
#define SM_P  (SM_V + 64 * VS_S2)
#define SM_TOT (SM_P + 128 * PS_S)   // uint32 count

__global__ __launch_bounds__(256, 1)
void attn_tf32(const float* __restrict__ qkv,
               const float* __restrict__ Kg,
               const float* __restrict__ Vg,
               float* __restrict__ Y) {
    extern __shared__ __align__(16) uint32_t smu[];
    uint32_t* Qs = smu + SM_Q;
    uint32_t* Ks = smu + SM_K;
    uint32_t* Vs = smu + SM_V;
    uint32_t* Ps = smu + SM_P;

    const int tid = threadIdx.x;
    const int lane = tid & 31;
    const int warp = tid >> 5;
    const int g4 = lane >> 2;      // 0..7
    const int a4 = lane & 3;       // 0..3

    const int qtile = (gridDim.x - 1) - blockIdx.x;   // heavy blocks first
    const int bh = blockIdx.y;
    const int b = bh >> 4, h = bh & 15;
    const int kv = h >> 2;

    // stage Q (128 x 128) as tf32
    const float* qbase = qkv + ((size_t)(b * TT + qtile * 128)) * N1 + h * DD;
#pragma unroll
    for (int i = 0; i < 16; i++) {
        int idx = tid + i * 256;
        int row = idx >> 5;
        int col = (idx & 31) * 4;
        float4 q = *(const float4*)(qbase + (size_t)row * N1 + col);
        uint4 t;
        t.x = f2tf32(q.x); t.y = f2tf32(q.y);
        t.z = f2tf32(q.z); t.w = f2tf32(q.w);
        *(uint4*)(Qs + row * QS_S + col) = t;
    }

    float oacc[16][4];
#pragma unroll
    for (int nt = 0; nt < 16; nt++)
#pragma unroll
        for (int r = 0; r < 4; r++) oacc[nt][r] = 0.f;
    float m0 = -1e30f, m1 = -1e30f, l0 = 0.f, l1 = 0.f;

    const float scale = 0.08838834764831845f;
    const float* kbase = Kg + ((size_t)(b * NKVH + kv) * TT) * DD;
    const float* vbase = Vg + ((size_t)(b * NKVH + kv) * TT) * DD;

    const int rloc = warp * 16 + g4;               // local row (lo)
    const int grow0 = qtile * 128 + rloc;          // global row lo
    const int grow1 = grow0 + 8;

    const int njt = 2 * qtile + 2;
    for (int jt = 0; jt < njt; jt++) {
        __syncthreads();
        // stage K,V (64 x 128), already tf32 bits
#pragma unroll
        for (int i = 0; i < 8; i++) {
            int idx = tid + i * 256;
            int tok = idx >> 5;
            int col = (idx & 31) * 4;
            const float4* kp = (const float4*)(kbase + (size_t)(jt * 64 + tok) * DD + col);
            const float4* vp = (const float4*)(vbase + (size_t)(jt * 64 + tok) * DD + col);
            *(uint4*)(Ks + tok * KS_S + col) = *(const uint4*)kp;
            *(uint4*)(Vs + tok * VS_S2 + col) = *(const uint4*)vp;
        }
        __syncthreads();

        // S = Q K^T : warp stripe m16 x n64
        float sacc[8][4];
#pragma unroll
        for (int nt = 0; nt < 8; nt++)
#pragma unroll
            for (int r = 0; r < 4; r++) sacc[nt][r] = 0.f;

#pragma unroll
        for (int kt = 0; kt < 16; kt++) {
            uint32_t af[4];
            int c = kt * 8 + a4;
            af[0] = Qs[rloc * QS_S + c];
            af[1] = Qs[(rloc + 8) * QS_S + c];
            af[2] = Qs[rloc * QS_S + c + 4];
            af[3] = Qs[(rloc + 8) * QS_S + c + 4];
#pragma unroll
            for (int nt = 0; nt < 8; nt++) {
                uint32_t bf[2];
                int n = nt * 8 + g4;
                bf[0] = Ks[n * KS_S + kt * 8 + a4];
                bf[1] = Ks[n * KS_S + kt * 8 + a4 + 4];
                mma_tf32(sacc[nt], af, bf);
            }
        }

        // scale + causal mask (only needed on the last two jt tiles)
        if (jt >= 2 * qtile) {
#pragma unroll
            for (int nt = 0; nt < 8; nt++) {
                int gc = jt * 64 + nt * 8 + 2 * a4;
                sacc[nt][0] = (gc     > grow0) ? -1e30f : sacc[nt][0] * scale;
                sacc[nt][1] = (gc + 1 > grow0) ? -1e30f : sacc[nt][1] * scale;
                sacc[nt][2] = (gc     > grow1) ? -1e30f : sacc[nt][2] * scale;
                sacc[nt][3] = (gc + 1 > grow1) ? -1e30f : sacc[nt][3] * scale;
            }
        } else {
#pragma unroll
            for (int nt = 0; nt < 8; nt++)
#pragma unroll
                for (int r = 0; r < 4; r++) sacc[nt][r] *= scale;
        }

        // online softmax (rows grow0 / grow1, quad-reduce)
        float rm0 = -1e30f, rm1 = -1e30f;
#pragma unroll
        for (int nt = 0; nt < 8; nt++) {
            rm0 = fmaxf(rm0, fmaxf(sacc[nt][0], sacc[nt][1]));
            rm1 = fmaxf(rm1, fmaxf(sacc[nt][2], sacc[nt][3]));
        }
        rm0 = fmaxf(rm0, __shfl_xor_sync(0xffffffffu, rm0, 1));
        rm0 = fmaxf(rm0, __shfl_xor_sync(0xffffffffu, rm0, 2));
        rm1 = fmaxf(rm1, __shfl_xor_sync(0xffffffffu, rm1, 1));
        rm1 = fmaxf(rm1, __shfl_xor_sync(0xffffffffu, rm1, 2));

        float mn0 = fmaxf(m0, rm0), mn1 = fmaxf(m1, rm1);
        float corr0 = __expf(m0 - mn0), corr1 = __expf(m1 - mn1);
        m0 = mn0; m1 = mn1;

        float rs0 = 0.f, rs1 = 0.f;
#pragma unroll
        for (int nt = 0; nt < 8; nt++) {
            float p0 = __expf(sacc[nt][0] - mn0);
            float p1 = __expf(sacc[nt][1] - mn0);
            float p2 = __expf(sacc[nt][2] - mn1);
            float p3 = __expf(sacc[nt][3] - mn1);
            rs0 += p0 + p1; rs1 += p2 + p3;
            int cc = nt * 8 + 2 * a4;
            uint2 lo = make_uint2(f2tf32(p0), f2tf32(p1));
            uint2 hi = make_uint2(f2tf32(p2), f2tf32(p3));
            *(uint2*)(Ps + rloc * PS_S + cc) = lo;
            *(uint2*)(Ps + (rloc + 8) * PS_S + cc) = hi;
        }
        rs0 += __shfl_xor_sync(0xffffffffu, rs0, 1);
        rs0 += __shfl_xor_sync(0xffffffffu, rs0, 2);
        rs1 += __shfl_xor_sync(0xffffffffu, rs1, 1);
        rs1 += __shfl_xor_sync(0xffffffffu, rs1, 2);
        l0 = l0 * corr0 + rs0;
        l1 = l1 * corr1 + rs1;

#pragma unroll
        for (int nt = 0; nt < 16; nt++) {
            oacc[nt][0] *= corr0; oacc[nt][1] *= corr0;
            oacc[nt][2] *= corr1; oacc[nt][3] *= corr1;
        }
        __syncwarp();

        // O += P V : m16 x n128, k=64
#pragma unroll
        for (int kt = 0; kt < 8; kt++) {
            uint32_t af[4];
            int c = kt * 8 + a4;
            af[0] = Ps[rloc * PS_S + c];
            af[1] = Ps[(rloc + 8) * PS_S + c];
            af[2] = Ps[rloc * PS_S + c + 4];
            af[3] = Ps[(rloc + 8) * PS_S + c + 4];
#pragma unroll
            for (int nt = 0; nt < 16; nt++) {
                uint32_t bf[2];
                bf[0] = Vs[(kt * 8 + a4) * VS_S2 + nt * 8 + g4];
                bf[1] = Vs[(kt * 8 + a4 + 4) * VS_S2 + nt * 8 + g4];
                mma_tf32(oacc[nt], af, bf);
            }
        }
    }

    // finalize
    float inv0 = 1.f / l0, inv1 = 1.f / l1;
    int t0 = qtile * 128 + rloc;
    float* y0 = Y + ((size_t)(b * TT + t0)) * EE + h * DD;
    float* y1 = Y + ((size_t)(b * TT + t0 + 8)) * EE + h * DD;
#pragma unroll
    for (int nt = 0; nt < 16; nt++) {
        int cc = nt * 8 + 2 * a4;
        *(float2*)(y0 + cc) = make_float2(oacc[nt][0] * inv0, oacc[nt][1] * inv0);
        *(float2*)(y1 + cc) = make_float2(oacc[nt][2] * inv1, oacc[nt][3] * inv1);
    }
}

// ---------------------------------------------------------------------------
extern "C" void kernel_launch(void* const* d_in, const int* in_sizes, int n_in,
                              void* d_out, int out_size) {
    const float* x  = (const float*)d_in[0];
    const float* Wa = (const float*)d_in[1];
    const float* ba = (const float*)d_in[2];
    const float* Wp = (const float*)d_in[3];
    const float* fc = (const float*)d_in[4];
    const float* fs = (const float*)d_in[5];
    float* out = (float*)d_out;

    float *qkv, *kg, *vg, *yb;
    cudaGetSymbolAddress((void**)&qkv, g_qkv);
    cudaGetSymbolAddress((void**)&kg, g_k);
    cudaGetSymbolAddress((void**)&vg, g_v);
    cudaGetSymbolAddress((void**)&yb, g_y);

    gemm_tf32<<<dim3(N1 / 128, MM / 128), 256>>>(x, Wa, ba, qkv, MM, N1, EE);
    rope_split_kernel<<<dim3(TT, BB * NKVH), 64>>>(qkv, fc, fs, kg, vg);

    int smem_bytes = SM_TOT * (int)sizeof(uint32_t);
    cudaFuncSetAttribute(attn_tf32, cudaFuncAttributeMaxDynamicSharedMemorySize,
                         smem_bytes);
    attn_tf32<<<dim3(TT / 128, BB * HH), 256, smem_bytes>>>(qkv, kg, vg, yb);

    gemm_tf32<<<dim3(EE / 128, MM / 128), 256>>>(yb, Wp, nullptr, out, MM, EE, EE);
}

// round 4
// speedup vs baseline: 4.1790x; 1.3646x over previous
#include <cuda_runtime.h>
#include <cuda_bf16.h>
#include <math.h>
#include <stdint.h>

// Problem constants (QwenGroupedQueryAttention_44100724195922)
#define BB   2
#define TT   2048
#define EE   2048
#define HH   16
#define DD   128
#define GG   4
#define NKVH 4
#define KVD  512
#define N1   3072
#define MM   4096

__device__ float g_qkv[(size_t)MM * N1];             // fp32
__device__ float g_k[(size_t)BB * NKVH * TT * DD];   // tf32 bits
__device__ float g_v[(size_t)BB * NKVH * TT * DD];   // tf32 bits
__device__ float g_y[(size_t)MM * EE];               // tf32 bits (attn out)
__device__ float g_xt[(size_t)MM * EE];              // x as tf32 bits
__device__ float g_wat[(size_t)N1 * EE];             // Wa^T [N1][E] tf32 bits
__device__ float g_wpt[(size_t)EE * EE];             // Wp^T [E][E] tf32 bits

__device__ __forceinline__ uint32_t f2tf32(float x) {
    uint32_t r;
    asm("cvt.rna.tf32.f32 %0, %1;" : "=r"(r) : "f"(x));
    return r;
}

__device__ __forceinline__ void mma_tf32(float c[4], const uint32_t a[4],
                                         const uint32_t b[2]) {
    asm volatile(
        "mma.sync.aligned.m16n8k8.row.col.f32.tf32.tf32.f32 "
        "{%0,%1,%2,%3}, {%4,%5,%6,%7}, {%8,%9}, {%0,%1,%2,%3};"
        : "+f"(c[0]), "+f"(c[1]), "+f"(c[2]), "+f"(c[3])
        : "r"(a[0]), "r"(a[1]), "r"(a[2]), "r"(a[3]), "r"(b[0]), "r"(b[1]));
}

__device__ __forceinline__ void cp16(uint32_t dst, const void* src) {
    asm volatile("cp.async.cg.shared.global [%0], [%1], 16;"
                 :: "r"(dst), "l"(src));
}
__device__ __forceinline__ void ldsm_x4(uint32_t* r, uint32_t a) {
    asm volatile("ldmatrix.sync.aligned.m8n8.x4.shared.b16 {%0,%1,%2,%3}, [%4];"
                 : "=r"(r[0]), "=r"(r[1]), "=r"(r[2]), "=r"(r[3]) : "r"(a));
}
__device__ __forceinline__ void ldsm_x2(uint32_t* r, uint32_t a) {
    asm volatile("ldmatrix.sync.aligned.m8n8.x2.shared.b16 {%0,%1}, [%2];"
                 : "=r"(r[0]), "=r"(r[1]) : "r"(a));
}

// ---------------------------------------------------------------------------
// Elementwise fp32 -> tf32 bits
// ---------------------------------------------------------------------------
__global__ __launch_bounds__(256)
void conv_tf32(const float* __restrict__ in, float* __restrict__ out, int n4) {
    int i = blockIdx.x * 256 + threadIdx.x;
    if (i >= n4) return;
    float4 v = ((const float4*)in)[i];
    uint4 t;
    t.x = f2tf32(v.x); t.y = f2tf32(v.y); t.z = f2tf32(v.z); t.w = f2tf32(v.w);
    ((uint4*)out)[i] = t;
}

// ---------------------------------------------------------------------------
// Transpose + tf32: W[K][N] -> Wt[N][K]
// ---------------------------------------------------------------------------
__global__ __launch_bounds__(256)
void transpose_tf32(const float* __restrict__ W, float* __restrict__ Wt,
                    int K, int N) {
    __shared__ float tile[32][33];
    int n0 = blockIdx.x * 32, k0 = blockIdx.y * 32;
    int tx = threadIdx.x, ty = threadIdx.y;  // (32, 8)
#pragma unroll
    for (int j = 0; j < 4; j++)
        tile[ty + j * 8][tx] = W[(size_t)(k0 + ty + j * 8) * N + n0 + tx];
    __syncthreads();
#pragma unroll
    for (int j = 0; j < 4; j++)
        Wt[(size_t)(n0 + ty + j * 8) * K + k0 + tx] =
            __uint_as_float(f2tf32(tile[tx][ty + j * 8]));
}

// ---------------------------------------------------------------------------
// TF32 GEMM v2: C[M,N] = A[M,K] @ Bt[N,K]^T (+bias)
// A, Bt hold tf32 bit patterns. 128x128 tile, BK=32, cp.async 3-stage,
// ldmatrix fragment loads, XOR-swizzled smem.
// ---------------------------------------------------------------------------
#define STAGES 3
#define STG_BYTES 16384   // 128 rows * 32 floats * 4B

__global__ __launch_bounds__(256, 2)
void gemm_v2(const float* __restrict__ A, const float* __restrict__ Bt,
             const float* __restrict__ bias, float* __restrict__ C,
             int M, int N, int K) {
    extern __shared__ __align__(16) char smraw[];
    uint32_t sA = (uint32_t)__cvta_generic_to_shared(smraw);
    uint32_t sB = sA + STAGES * STG_BYTES;

    const int tid = threadIdx.x;
    const int lane = tid & 31;
    const int wid = tid >> 5;
    const int wm = wid >> 2;   // 0..1
    const int wn = wid & 3;    // 0..3
    const int bm = blockIdx.y * 128, bn = blockIdx.x * 128;

    float acc[4][4][4];
#pragma unroll
    for (int mi = 0; mi < 4; mi++)
#pragma unroll
        for (int ni = 0; ni < 4; ni++)
#pragma unroll
            for (int r = 0; r < 4; r++) acc[mi][ni][r] = 0.f;

    const int srow = tid >> 3;        // staging row block offset (0..31)
    const int sk4 = tid & 7;          // staging k4

    auto stage_fn = [&](int kt, int stg) {
#pragma unroll
        for (int i = 0; i < 4; i++) {
            int row = srow + i * 32;
            uint32_t dst = sA + stg * STG_BYTES +
                           ((row * 8 + (sk4 ^ (row & 7))) << 4);
            cp16(dst, A + (size_t)(bm + row) * K + kt * 32 + sk4 * 4);
        }
#pragma unroll
        for (int i = 0; i < 4; i++) {
            int row = srow + i * 32;
            uint32_t dst = sB + stg * STG_BYTES +
                           ((row * 8 + (sk4 ^ (row & 7))) << 4);
            cp16(dst, Bt + (size_t)(bn + row) * K + kt * 32 + sk4 * 4);
        }
        asm volatile("cp.async.commit_group;");
    };

    const int nkt = K / 32;
    stage_fn(0, 0);
    if (nkt > 1) stage_fn(1, 1);

    // ldmatrix lane address components
    const int mLane = wm * 64 + (lane & 15);       // + mi*16
    const int k4A_base = (lane >> 4);              // + s*2
    const int nLane = wn * 32 + (lane & 7);        // + ni*8
    const int k4B_base = ((lane >> 3) & 1);        // + s*2

    for (int kt = 0; kt < nkt; kt++) {
        int cur = kt % STAGES;
        asm volatile("cp.async.wait_group 1;");
        __syncthreads();
        if (kt + 2 < nkt) stage_fn(kt + 2, (kt + 2) % STAGES);

        uint32_t aBase = sA + cur * STG_BYTES;
        uint32_t bBase = sB + cur * STG_BYTES;
#pragma unroll
        for (int s = 0; s < 4; s++) {
            uint32_t af[4][4];
            int k4a = s * 2 + k4A_base;
#pragma unroll
            for (int mi = 0; mi < 4; mi++) {
                int m = mLane + mi * 16;
                ldsm_x4(af[mi], aBase + ((m * 8 + (k4a ^ (m & 7))) << 4));
            }
            uint32_t bf[4][2];
            int k4b = s * 2 + k4B_base;
#pragma unroll
            for (int ni = 0; ni < 4; ni++) {
                int n = nLane + ni * 8;
                ldsm_x2(bf[ni], bBase + ((n * 8 + (k4b ^ (n & 7))) << 4));
            }
#pragma unroll
            for (int mi = 0; mi < 4; mi++)
#pragma unroll
                for (int ni = 0; ni < 4; ni++)
                    mma_tf32(acc[mi][ni], af[mi], bf[ni]);
        }
        __syncthreads();
    }

    const int g4 = lane >> 2, a4 = lane & 3;
#pragma unroll
    for (int mi = 0; mi < 4; mi++) {
        int row = bm + wm * 64 + mi * 16 + g4;
#pragma unroll
        for (int ni = 0; ni < 4; ni++) {
            int col = bn + wn * 32 + ni * 8 + 2 * a4;
            float bx = 0.f, by = 0.f;
            if (bias) { bx = bias[col]; by = bias[col + 1]; }
            *(float2*)(C + (size_t)row * N + col) =
                make_float2(acc[mi][ni][0] + bx, acc[mi][ni][1] + by);
            *(float2*)(C + (size_t)(row + 8) * N + col) =
                make_float2(acc[mi][ni][2] + bx, acc[mi][ni][3] + by);
        }
    }
}

// ---------------------------------------------------------------------------
// RoPE on K and V, split into [B,NKV,T,D], stored as TF32 bits.
// ---------------------------------------------------------------------------
__global__ __launch_bounds__(64)
void rope_split_kernel(const float* __restrict__ qkv,
                       const float* __restrict__ fc,
                       const float* __restrict__ fs,
                       float* __restrict__ Kg, float* __restrict__ Vg) {
    int t = blockIdx.x;
    int bk = blockIdx.y;
    int b = bk / NKVH, kv = bk % NKVH;
    int i = threadIdx.x;

    float c = fc[t * 64 + i];
    float s = fs[t * 64 + i];
    const float* row = qkv + ((size_t)(b * TT + t)) * N1;

    float k0 = row[EE + kv * DD + 2 * i];
    float k1 = row[EE + kv * DD + 2 * i + 1];
    float v0 = row[EE + KVD + kv * DD + 2 * i];
    float v1 = row[EE + KVD + kv * DD + 2 * i + 1];

    size_t o = ((size_t)(b * NKVH + kv) * TT + t) * DD + 2 * i;
    Kg[o]     = __uint_as_float(f2tf32(k0 * c - k1 * s));
    Kg[o + 1] = __uint_as_float(f2tf32(k0 * s + k1 * c));
    Vg[o]     = __uint_as_float(f2tf32(v0 * c - v1 * s));
    Vg[o + 1] = __uint_as_float(f2tf32(v0 * s + v1 * c));
}

// ---------------------------------------------------------------------------
// TF32 tensor-core flash attention (as R3), output stored as tf32 bits.
// ---------------------------------------------------------------------------
#define QS_S 132
#define KS_S 132
#define VS_S2 136
#define PS_S 68
#define SM_Q  0
#define SM_K  (128 * QS_S)
#define SM_V  (SM_K + 64 * KS_S)
#define SM_P  (SM_V + 64 * VS_S2)
#define SM_TOT (SM_P + 128 * PS_S)

__global__ __launch_bounds__(256, 1)
void attn_tf32(const float* __restrict__ qkv,
               const float* __restrict__ Kg,
               const float* __restrict__ Vg,
               float* __restrict__ Y) {
    extern __shared__ __align__(16) uint32_t smu[];
    uint32_t* Qs = smu + SM_Q;
    uint32_t* Ks = smu + SM_K;
    uint32_t* Vs = smu + SM_V;
    uint32_t* Ps = smu + SM_P;

    const int tid = threadIdx.x;
    const int lane = tid & 31;
    const int warp = tid >> 5;
    const int g4 = lane >> 2;
    const int a4 = lane & 3;

    const int qtile = (gridDim.x - 1) - blockIdx.x;
    const int bh = blockIdx.y;
    const int b = bh >> 4, h = bh & 15;
    const int kv = h >> 2;

    const float* qbase = qkv + ((size_t)(b * TT + qtile * 128)) * N1 + h * DD;
#pragma unroll
    for (int i = 0; i < 16; i++) {
        int idx = tid + i * 256;
        int row = idx >> 5;
        int col = (idx & 31) * 4;
        float4 q = *(const float4*)(qbase + (size_t)row * N1 + col);
        uint4 t;
        t.x = f2tf32(q.x); t.y = f2tf32(q.y);
        t.z = f2tf32(q.z); t.w = f2tf32(q.w);
        *(uint4*)(Qs + row * QS_S + col) = t;
    }

    float oacc[16][4];
#pragma unroll
    for (int nt = 0; nt < 16; nt++)
#pragma unroll
        for (int r = 0; r < 4; r++) oacc[nt][r] = 0.f;
    float m0 = -1e30f, m1 = -1e30f, l0 = 0.f, l1 = 0.f;

    const float scale = 0.08838834764831845f;
    const float* kbase = Kg + ((size_t)(b * NKVH + kv) * TT) * DD;
    const float* vbase = Vg + ((size_t)(b * NKVH + kv) * TT) * DD;

    const int rloc = warp * 16 + g4;
    const int grow0 = qtile * 128 + rloc;
    const int grow1 = grow0 + 8;

    const int njt = 2 * qtile + 2;
    for (int jt = 0; jt < njt; jt++) {
        __syncthreads();
#pragma unroll
        for (int i = 0; i < 8; i++) {
            int idx = tid + i * 256;
            int tok = idx >> 5;
            int col = (idx & 31) * 4;
            const float4* kp = (const float4*)(kbase + (size_t)(jt * 64 + tok) * DD + col);
            const float4* vp = (const float4*)(vbase + (size_t)(jt * 64 + tok) * DD + col);
            *(uint4*)(Ks + tok * KS_S + col) = *(const uint4*)kp;
            *(uint4*)(Vs + tok * VS_S2 + col) = *(const uint4*)vp;
        }
        __syncthreads();

        float sacc[8][4];
#pragma unroll
        for (int nt = 0; nt < 8; nt++)
#pragma unroll
            for (int r = 0; r < 4; r++) sacc[nt][r] = 0.f;

#pragma unroll
        for (int kt = 0; kt < 16; kt++) {
            uint32_t af[4];
            int c = kt * 8 + a4;
            af[0] = Qs[rloc * QS_S + c];
            af[1] = Qs[(rloc + 8) * QS_S + c];
            af[2] = Qs[rloc * QS_S + c + 4];
            af[3] = Qs[(rloc + 8) * QS_S + c + 4];
#pragma unroll
            for (int nt = 0; nt < 8; nt++) {
                uint32_t bf[2];
                int n = nt * 8 + g4;
                bf[0] = Ks[n * KS_S + kt * 8 + a4];
                bf[1] = Ks[n * KS_S + kt * 8 + a4 + 4];
                mma_tf32(sacc[nt], af, bf);
            }
        }

        if (jt >= 2 * qtile) {
#pragma unroll
            for (int nt = 0; nt < 8; nt++) {
                int gc = jt * 64 + nt * 8 + 2 * a4;
                sacc[nt][0] = (gc     > grow0) ? -1e30f : sacc[nt][0] * scale;
                sacc[nt][1] = (gc + 1 > grow0) ? -1e30f : sacc[nt][1] * scale;
                sacc[nt][2] = (gc     > grow1) ? -1e30f : sacc[nt][2] * scale;
                sacc[nt][3] = (gc + 1 > grow1) ? -1e30f : sacc[nt][3] * scale;
            }
        } else {
#pragma unroll
            for (int nt = 0; nt < 8; nt++)
#pragma unroll
                for (int r = 0; r < 4; r++) sacc[nt][r] *= scale;
        }

        float rm0 = -1e30f, rm1 = -1e30f;
#pragma unroll
        for (int nt = 0; nt < 8; nt++) {
            rm0 = fmaxf(rm0, fmaxf(sacc[nt][0], sacc[nt][1]));
            rm1 = fmaxf(rm1, fmaxf(sacc[nt][2], sacc[nt][3]));
        }
        rm0 = fmaxf(rm0, __shfl_xor_sync(0xffffffffu, rm0, 1));
        rm0 = fmaxf(rm0, __shfl_xor_sync(0xffffffffu, rm0, 2));
        rm1 = fmaxf(rm1, __shfl_xor_sync(0xffffffffu, rm1, 1));
        rm1 = fmaxf(rm1, __shfl_xor_sync(0xffffffffu, rm1, 2));

        float mn0 = fmaxf(m0, rm0), mn1 = fmaxf(m1, rm1);
        float corr0 = __expf(m0 - mn0), corr1 = __expf(m1 - mn1);
        m0 = mn0; m1 = mn1;

        float rs0 = 0.f, rs1 = 0.f;
#pragma unroll
        for (int nt = 0; nt < 8; nt++) {
            float p0 = __expf(sacc[nt][0] - mn0);
            float p1 = __expf(sacc[nt][1] - mn0);
            float p2 = __expf(sacc[nt][2] - mn1);
            float p3 = __expf(sacc[nt][3] - mn1);
            rs0 += p0 + p1; rs1 += p2 + p3;
            int cc = nt * 8 + 2 * a4;
            *(uint2*)(Ps + rloc * PS_S + cc) = make_uint2(f2tf32(p0), f2tf32(p1));
            *(uint2*)(Ps + (rloc + 8) * PS_S + cc) = make_uint2(f2tf32(p2), f2tf32(p3));
        }
        rs0 += __shfl_xor_sync(0xffffffffu, rs0, 1);
        rs0 += __shfl_xor_sync(0xffffffffu, rs0, 2);
        rs1 += __shfl_xor_sync(0xffffffffu, rs1, 1);
        rs1 += __shfl_xor_sync(0xffffffffu, rs1, 2);
        l0 = l0 * corr0 + rs0;
        l1 = l1 * corr1 + rs1;

#pragma unroll
        for (int nt = 0; nt < 16; nt++) {
            oacc[nt][0] *= corr0; oacc[nt][1] *= corr0;
            oacc[nt][2] *= corr1; oacc[nt][3] *= corr1;
        }
        __syncwarp();

#pragma unroll
        for (int kt = 0; kt < 8; kt++) {
            uint32_t af[4];
            int c = kt * 8 + a4;
            af[0] = Ps[rloc * PS_S + c];
            af[1] = Ps[(rloc + 8) * PS_S + c];
            af[2] = Ps[rloc * PS_S + c + 4];
            af[3] = Ps[(rloc + 8) * PS_S + c + 4];
#pragma unroll
            for (int nt = 0; nt < 16; nt++) {
                uint32_t bf[2];
                bf[0] = Vs[(kt * 8 + a4) * VS_S2 + nt * 8 + g4];
                bf[1] = Vs[(kt * 8 + a4 + 4) * VS_S2 + nt * 8 + g4];
                mma_tf32(oacc[nt], af, bf);
            }
        }
    }

    // finalize: write tf32 bits (valid fp32) so proj GEMM can cp.async directly
    float inv0 = 1.f / l0, inv1 = 1.f / l1;
    int t0 = qtile * 128 + rloc;
    float* y0 = Y + ((size_t)(b * TT + t0)) * EE + h * DD;
    float* y1 = Y + ((size_t)(b * TT + t0 + 8)) * EE + h * DD;
#pragma unroll
    for (int nt = 0; nt < 16; nt++) {
        int cc = nt * 8 + 2 * a4;
        *(float2*)(y0 + cc) = make_float2(
            __uint_as_float(f2tf32(oacc[nt][0] * inv0)),
            __uint_as_float(f2tf32(oacc[nt][1] * inv0)));
        *(float2*)(y1 + cc) = make_float2(
            __uint_as_float(f2tf32(oacc[nt][2] * inv1)),
            __uint_as_float(f2tf32(oacc[nt][3] * inv1)));
    }
}

// ---------------------------------------------------------------------------
extern "C" void kernel_launch(void* const* d_in, const int* in_sizes, int n_in,
                              void* d_out, int out_size) {
    const float* x  = (const float*)d_in[0];
    const float* Wa = (const float*)d_in[1];
    const float* ba = (const float*)d_in[2];
    const float* Wp = (const float*)d_in[3];
    const float* fc = (const float*)d_in[4];
    const float* fs = (const float*)d_in[5];
    float* out = (float*)d_out;

    float *qkv, *kg, *vg, *yb, *xt, *wat, *wpt;
    cudaGetSymbolAddress((void**)&qkv, g_qkv);
    cudaGetSymbolAddress((void**)&kg, g_k);
    cudaGetSymbolAddress((void**)&vg, g_v);
    cudaGetSymbolAddress((void**)&yb, g_y);
    cudaGetSymbolAddress((void**)&xt, g_xt);
    cudaGetSymbolAddress((void**)&wat, g_wat);
    cudaGetSymbolAddress((void**)&wpt, g_wpt);

    // operand prep
    conv_tf32<<<(MM * EE / 4 + 255) / 256, 256>>>(x, xt, MM * EE / 4);
    transpose_tf32<<<dim3(N1 / 32, EE / 32), dim3(32, 8)>>>(Wa, wat, EE, N1);
    transpose_tf32<<<dim3(EE / 32, EE / 32), dim3(32, 8)>>>(Wp, wpt, EE, EE);

    int gsm = STAGES * STG_BYTES * 2;
    cudaFuncSetAttribute(gemm_v2, cudaFuncAttributeMaxDynamicSharedMemorySize, gsm);

    // 1) QKV GEMM (+bias)
    gemm_v2<<<dim3(N1 / 128, MM / 128), 256, gsm>>>(xt, wat, ba, qkv, MM, N1, EE);

    // 2) RoPE on K and V
    rope_split_kernel<<<dim3(TT, BB * NKVH), 64>>>(qkv, fc, fs, kg, vg);

    // 3) attention
    int smem_bytes = SM_TOT * (int)sizeof(uint32_t);
    cudaFuncSetAttribute(attn_tf32, cudaFuncAttributeMaxDynamicSharedMemorySize,
                         smem_bytes);
    attn_tf32<<<dim3(TT / 128, BB * HH), 256, smem_bytes>>>(qkv, kg, vg, yb);

    // 4) output projection
    gemm_v2<<<dim3(EE / 128, MM / 128), 256, gsm>>>(yb, wpt, nullptr, out, MM, EE, EE);
}